// round 2
// baseline (speedup 1.0000x reference)
#include <cuda_runtime.h>
#include <cuda_fp16.h>
#include <stdint.h>

// ---------------- problem constants ----------------
#define NNODES 50000
#define NEDGES 1000000
#define HID    128
#define KDIM   288            // 273 padded to 18 * 16
#define KSTEPS 18
#define STRH   296            // halves per smem row (592 B; 592 % 128 = 80 -> conflict-free ldmatrix)
#define STRB   592            // bytes per smem row
#define GROUPS (NEDGES / 16)  // 62500, exact (no tail)

// ---------------- smem layout (byte offsets) ----------------
#define SOFF_A    0            // 128 rows * 592  = 75776
#define SOFF_B    75776        // 128 rows * 592  = 75776
#define SOFF_DIFF 151552       // 8 warps * 16 * float4 = 2048
#define SOFF_ROW  153600       // 8 warps * 16 * int    = 512
#define SOFF_B1   154112       // 128 f32 = 512
#define SOFF_W2   154624       // 384 f32 = 1536
#define SOFF_B2   156160       // 16
#define SMEM_DYN  156288

// ---------------- device globals (no allocation allowed) ----------------
__device__ __half g_featH[(size_t)NNODES * HID];
__device__ __half g_W1h[HID * KDIM];     // [n][k] fp16, zero-padded k>=273
__device__ float  g_cnt[NNODES];

static __device__ __forceinline__ uint32_t smem_u32(const void* p) {
    uint32_t a;
    asm("{ .reg .u64 t; cvta.to.shared.u64 t, %1; cvt.u32.u64 %0, t; }" : "=r"(a) : "l"(p));
    return a;
}
static __device__ __forceinline__ float silu(float x) { return x / (1.f + __expf(-x)); }

// ---------------- prep kernels ----------------
__global__ void prep_feat_kernel(const float* __restrict__ nf) {
    int i = blockIdx.x * blockDim.x + threadIdx.x;
    const int tot = NNODES * HID / 2;
    if (i < tot) {
        float2 v = reinterpret_cast<const float2*>(nf)[i];
        reinterpret_cast<__half2*>(g_featH)[i] = __floats2half2_rn(v.x, v.y);
    }
}

// our k-order: [0..127]=feat_row, [128..255]=feat_col, [256..271]=edge_attr, [272]=dist, pad->288
// msg order  : [0]=dist, [1..128]=feat_row, [129..256]=feat_col, [257..272]=edge_attr
__global__ void prep_w1_kernel(const float* __restrict__ W1) {
    int idx = blockIdx.x * blockDim.x + threadIdx.x;
    if (idx >= HID * KDIM) return;
    int n = idx / KDIM, k = idx % KDIM;
    float v = 0.f;
    if (k < 273) {
        int orig = (k == 272) ? 0 : (k + 1);
        v = W1[orig * HID + n];
    }
    g_W1h[n * KDIM + k] = __float2half(v);
}

__global__ void zero_kernel(float* __restrict__ out) {
    int i = blockIdx.x * blockDim.x + threadIdx.x;
    int stride = gridDim.x * blockDim.x;
    for (int j = i; j < NNODES * 9; j += stride) out[j] = 0.f;
    for (int j = i; j < NNODES; j += stride) g_cnt[j] = 0.f;
}

__global__ void finalize_kernel(float* __restrict__ out) {
    int i = blockIdx.x * blockDim.x + threadIdx.x;
    int stride = gridDim.x * blockDim.x;
    for (int j = i; j < NNODES * 9; j += stride)
        out[j] = out[j] / fmaxf(g_cnt[j / 9], 1.0f);
}

// ---------------- main persistent kernel ----------------
__global__ void __launch_bounds__(256, 1)
edge_kernel(const float* __restrict__ pos,
            const float* __restrict__ edge_attr,
            const float* __restrict__ b1,
            const float* __restrict__ W2,
            const float* __restrict__ b2,
            const int*   __restrict__ ei,
            float*       __restrict__ out)
{
    extern __shared__ char sm[];
    const uint32_t smb = smem_u32(sm);
    const int tid = threadIdx.x;
    const int wid = tid >> 5;
    const int lid = tid & 31;

    // stage W1 [n][k] fp16 into smem with padded row stride
    {
        const uint32_t* src = reinterpret_cast<const uint32_t*>(g_W1h);
        uint32_t* dst = reinterpret_cast<uint32_t*>(sm + SOFF_B);
        for (int i = tid; i < HID * (KDIM / 2); i += 256) {
            int n = i / (KDIM / 2), k2 = i % (KDIM / 2);
            dst[n * (STRH / 2) + k2] = src[i];
        }
    }
    float* b1s = reinterpret_cast<float*>(sm + SOFF_B1);
    float* w2s = reinterpret_cast<float*>(sm + SOFF_W2);
    float* b2s = reinterpret_cast<float*>(sm + SOFF_B2);
    if (tid < HID) b1s[tid] = b1[tid];
    for (int i = tid; i < HID * 3; i += 256) w2s[i] = W2[i];
    if (tid < 3) b2s[tid] = b2[tid];
    __syncthreads();

    __half* Aw   = reinterpret_cast<__half*>(sm + SOFF_A) + wid * 16 * STRH;
    float4* sdif = reinterpret_cast<float4*>(sm + SOFF_DIFF) + wid * 16;
    int*    srw  = reinterpret_cast<int*>(sm + SOFF_ROW) + wid * 16;

    // ldmatrix lane address templates
    const int arow = (lid & 7) + ((lid >> 3) & 1) * 8;
    const int acol = ((lid >> 4) & 1) * 8;
    const uint32_t aAddr0 = smb + SOFF_A + (uint32_t)(wid * 16 + arow) * STRB + acol * 2;
    const int brow = lid & 7;
    const int bcol = ((lid >> 3) & 1) * 8;
    const uint32_t bAddr0 = smb + SOFF_B + (uint32_t)brow * STRB + bcol * 2;

    const int gstride = gridDim.x * 8;
    for (int g = blockIdx.x * 8 + wid; g < GROUPS; g += gstride) {
        const int e0 = g * 16;

        // ---- phase A: per-edge meta (lanes 0-15, one edge each) ----
        int r_reg = 0, c_reg = 0;
        if (lid < 16) {
            int e = e0 + lid;
            r_reg = ei[e];
            c_reg = ei[NEDGES + e];
            float dx = pos[3 * r_reg + 0] - pos[3 * c_reg + 0];
            float dy = pos[3 * r_reg + 1] - pos[3 * c_reg + 1];
            float dz = pos[3 * r_reg + 2] - pos[3 * c_reg + 2];
            float d = sqrtf(dx * dx + dy * dy + dz * dz);
            sdif[lid] = make_float4(dx, dy, dz, d);
            srw[lid] = r_reg;
            __half* Ar = Aw + lid * STRH;
            #pragma unroll
            for (int k2 = 274; k2 < 288; k2 += 2)
                *reinterpret_cast<uint32_t*>(Ar + k2) = 0u;
            __half2 dh = __floats2half2_rn(d, 0.f);
            *reinterpret_cast<__half2*>(Ar + 272) = dh;
        }
        __syncwarp();

        // ---- phase B: gather features + edge_attr into A rows ----
        #pragma unroll 1
        for (int i = 0; i < 16; ++i) {
            int r = __shfl_sync(0xffffffffu, r_reg, i);
            int c = __shfl_sync(0xffffffffu, c_reg, i);
            __half* Ar = Aw + i * STRH;
            const uint2* fr = reinterpret_cast<const uint2*>(g_featH + (size_t)r * HID);
            const uint2* fc = reinterpret_cast<const uint2*>(g_featH + (size_t)c * HID);
            *reinterpret_cast<uint2*>(Ar + 4 * lid)       = fr[lid];
            *reinterpret_cast<uint2*>(Ar + 128 + 4 * lid) = fc[lid];
            if (lid < 8) {
                float2 a2 = reinterpret_cast<const float2*>(edge_attr)[(size_t)(e0 + i) * 8 + lid];
                *reinterpret_cast<__half2*>(Ar + 256 + 2 * lid) = __floats2half2_rn(a2.x, a2.y);
            }
        }
        __syncwarp();

        // ---- GEMM1: D[16x128] = A[16x288] * W1^T, fp32 accum in registers ----
        float acc[16][4];
        #pragma unroll
        for (int nt = 0; nt < 16; ++nt) {
            acc[nt][0] = 0.f; acc[nt][1] = 0.f; acc[nt][2] = 0.f; acc[nt][3] = 0.f;
        }
        uint32_t aA = aAddr0;
        uint32_t bA = bAddr0;
        #pragma unroll 1
        for (int ks = 0; ks < KSTEPS; ++ks) {
            uint32_t a0, a1, a2r, a3;
            asm volatile("ldmatrix.sync.aligned.m8n8.x4.shared.b16 {%0,%1,%2,%3}, [%4];"
                         : "=r"(a0), "=r"(a1), "=r"(a2r), "=r"(a3) : "r"(aA));
            #pragma unroll
            for (int nt = 0; nt < 16; ++nt) {
                uint32_t b0, b1r;
                asm volatile("ldmatrix.sync.aligned.m8n8.x2.shared.b16 {%0,%1}, [%2];"
                             : "=r"(b0), "=r"(b1r) : "r"(bA + (uint32_t)nt * 8 * STRB));
                asm volatile("mma.sync.aligned.m16n8k16.row.col.f32.f16.f16.f32 "
                             "{%0,%1,%2,%3}, {%4,%5,%6,%7}, {%8,%9}, {%0,%1,%2,%3};"
                             : "+f"(acc[nt][0]), "+f"(acc[nt][1]), "+f"(acc[nt][2]), "+f"(acc[nt][3])
                             : "r"(a0), "r"(a1), "r"(a2r), "r"(a3), "r"(b0), "r"(b1r));
            }
            aA += 32;
            bA += 32;
        }

        // ---- epilogue: silu(h+b1), dot with W2 (3 cols), quad-reduce ----
        float p00 = 0.f, p01 = 0.f, p02 = 0.f, p10 = 0.f, p11 = 0.f, p12 = 0.f;
        const int cbase = (lid & 3) * 2;
        #pragma unroll
        for (int nt = 0; nt < 16; ++nt) {
            int n = nt * 8 + cbase;
            float h0 = silu(acc[nt][0] + b1s[n]);
            float h1 = silu(acc[nt][1] + b1s[n + 1]);
            float h2 = silu(acc[nt][2] + b1s[n]);
            float h3 = silu(acc[nt][3] + b1s[n + 1]);
            float wa0 = w2s[n * 3 + 0], wb0 = w2s[n * 3 + 1], wc0 = w2s[n * 3 + 2];
            float wa1 = w2s[n * 3 + 3], wb1 = w2s[n * 3 + 4], wc1 = w2s[n * 3 + 5];
            p00 += h0 * wa0 + h1 * wa1;
            p01 += h0 * wb0 + h1 * wb1;
            p02 += h0 * wc0 + h1 * wc1;
            p10 += h2 * wa0 + h3 * wa1;
            p11 += h2 * wb0 + h3 * wb1;
            p12 += h2 * wc0 + h3 * wc1;
        }
        #pragma unroll
        for (int off = 1; off <= 2; off <<= 1) {
            p00 += __shfl_xor_sync(0xffffffffu, p00, off);
            p01 += __shfl_xor_sync(0xffffffffu, p01, off);
            p02 += __shfl_xor_sync(0xffffffffu, p02, off);
            p10 += __shfl_xor_sync(0xffffffffu, p10, off);
            p11 += __shfl_xor_sync(0xffffffffu, p11, off);
            p12 += __shfl_xor_sync(0xffffffffu, p12, off);
        }

        if ((lid & 3) == 0) {
            const int gq = lid >> 2;
            const float s3 = 1.7320508075688772f;
            #pragma unroll
            for (int half = 0; half < 2; ++half) {
                int rowi = gq + half * 8;
                float pa = half ? p10 : p00;
                float pb = half ? p11 : p01;
                float pc = half ? p12 : p02;
                float w0 = silu(pa + b2s[0]);
                float w1 = silu(pb + b2s[1]);
                float w2v = silu(pc + b2s[2]);
                float4 dd = sdif[rowi];
                float inv = 1.f / fmaxf(dd.w, 1e-12f);
                float x = dd.x * inv, y = dd.y * inv, z = dd.z * inv;
                int rn = srw[rowi];
                float* o = out + (size_t)rn * 9;
                atomicAdd(o + 0, w0);
                atomicAdd(o + 1, x * w1);
                atomicAdd(o + 2, y * w1);
                atomicAdd(o + 3, z * w1);
                atomicAdd(o + 4, s3 * x * z * w2v);
                atomicAdd(o + 5, s3 * x * y * w2v);
                atomicAdd(o + 6, (y * y - 0.5f * (x * x + z * z)) * w2v);
                atomicAdd(o + 7, s3 * y * z * w2v);
                atomicAdd(o + 8, 0.5f * s3 * (z * z - x * x) * w2v);
                atomicAdd(&g_cnt[rn], 1.0f);
            }
        }
        // no CTA barrier needed: all hot-loop state is warp-private
    }
}

// ---------------- launch ----------------
extern "C" void kernel_launch(void* const* d_in, const int* in_sizes, int n_in,
                              void* d_out, int out_size) {
    const float* node_feat = (const float*)d_in[0];
    const float* node_pos  = (const float*)d_in[1];
    const float* edge_attr = (const float*)d_in[2];
    const float* W1        = (const float*)d_in[3];
    const float* b1        = (const float*)d_in[4];
    const float* W2        = (const float*)d_in[5];
    const float* b2        = (const float*)d_in[6];
    const int*   ei        = (const int*)d_in[7];
    float* out = (float*)d_out;

    cudaFuncSetAttribute(edge_kernel,
                         cudaFuncAttributeMaxDynamicSharedMemorySize, SMEM_DYN);

    zero_kernel<<<512, 256>>>(out);
    prep_feat_kernel<<<(NNODES * HID / 2 + 255) / 256, 256>>>(node_feat);
    prep_w1_kernel<<<(HID * KDIM + 255) / 256, 256>>>(W1);
    edge_kernel<<<152, 256, SMEM_DYN>>>(node_pos, edge_attr, b1, W2, b2, ei, out);
    finalize_kernel<<<512, 256>>>(out);
}

// round 3
// speedup vs baseline: 1.6956x; 1.6956x over previous
#include <cuda_runtime.h>
#include <cuda_fp16.h>
#include <stdint.h>

// ---------------- problem constants ----------------
#define NNODES 50000
#define NEDGES 1000000
#define HID    128
#define KDIM   288            // 273 padded to 18 * 16
#define KSTEPS 18
#define STRH   296            // halves per smem row (592 B; 592 % 128 = 80 -> conflict-free ldmatrix)
#define STRB   592            // bytes per smem row
#define GROUPS (NEDGES / 16)  // 62500, exact (no tail)
#define WPB    16             // warps per block
#define THREADS 512

// ---------------- smem layout (byte offsets) ----------------
#define SOFF_A    0            // 256 rows * 592 = 151552
#define SOFF_B    151552       // 128 rows * 592 = 75776  -> ends 227328
#define SOFF_B1   227328       // 128 f32 = 512
#define SOFF_W2   227840       // 384 f32 = 1536
#define SOFF_B2   229376       // 16
#define SMEM_DYN  229392

// ---------------- device globals (no allocation allowed) ----------------
__device__ __half g_featH[(size_t)NNODES * HID];
__device__ __half g_W1h[HID * KDIM];     // [n][k] fp16, zero-padded k>=273
__device__ float  g_cnt[NNODES];

static __device__ __forceinline__ uint32_t smem_u32(const void* p) {
    uint32_t a;
    asm("{ .reg .u64 t; cvta.to.shared.u64 t, %1; cvt.u32.u64 %0, t; }" : "=r"(a) : "l"(p));
    return a;
}
static __device__ __forceinline__ float silu(float x) { return x / (1.f + __expf(-x)); }

// ---------------- prep kernels ----------------
__global__ void prep_feat_kernel(const float* __restrict__ nf) {
    int i = blockIdx.x * blockDim.x + threadIdx.x;
    const int tot = NNODES * HID / 2;
    if (i < tot) {
        float2 v = reinterpret_cast<const float2*>(nf)[i];
        reinterpret_cast<__half2*>(g_featH)[i] = __floats2half2_rn(v.x, v.y);
    }
}

// our k-order: [0..127]=feat_row, [128..255]=feat_col, [256..271]=edge_attr, [272]=dist, pad->288
// msg order  : [0]=dist, [1..128]=feat_row, [129..256]=feat_col, [257..272]=edge_attr
__global__ void prep_w1_kernel(const float* __restrict__ W1) {
    int idx = blockIdx.x * blockDim.x + threadIdx.x;
    if (idx >= HID * KDIM) return;
    int n = idx / KDIM, k = idx % KDIM;
    float v = 0.f;
    if (k < 273) {
        int orig = (k == 272) ? 0 : (k + 1);
        v = W1[orig * HID + n];
    }
    g_W1h[n * KDIM + k] = __float2half(v);
}

__global__ void zero_kernel(float* __restrict__ out) {
    int i = blockIdx.x * blockDim.x + threadIdx.x;
    int stride = gridDim.x * blockDim.x;
    for (int j = i; j < NNODES * 9; j += stride) out[j] = 0.f;
    for (int j = i; j < NNODES; j += stride) g_cnt[j] = 0.f;
}

__global__ void finalize_kernel(float* __restrict__ out) {
    int i = blockIdx.x * blockDim.x + threadIdx.x;
    int stride = gridDim.x * blockDim.x;
    for (int j = i; j < NNODES * 9; j += stride)
        out[j] = out[j] / fmaxf(g_cnt[j / 9], 1.0f);
}

// ---------------- main persistent kernel ----------------
__global__ void __launch_bounds__(THREADS, 1)
edge_kernel(const float* __restrict__ pos,
            const float* __restrict__ edge_attr,
            const float* __restrict__ b1,
            const float* __restrict__ W2,
            const float* __restrict__ b2,
            const int*   __restrict__ ei,
            float*       __restrict__ out)
{
    extern __shared__ char sm[];
    const uint32_t smb = smem_u32(sm);
    const int tid = threadIdx.x;
    const int wid = tid >> 5;
    const int lid = tid & 31;

    // stage W1 [n][k] fp16 into smem with padded row stride
    {
        const uint32_t* src = reinterpret_cast<const uint32_t*>(g_W1h);
        uint32_t* dst = reinterpret_cast<uint32_t*>(sm + SOFF_B);
        for (int i = tid; i < HID * (KDIM / 2); i += THREADS) {
            int n = i / (KDIM / 2), k2 = i % (KDIM / 2);
            dst[n * (STRH / 2) + k2] = src[i];
        }
    }
    float* b1s = reinterpret_cast<float*>(sm + SOFF_B1);
    float* w2s = reinterpret_cast<float*>(sm + SOFF_W2);
    float* b2s = reinterpret_cast<float*>(sm + SOFF_B2);
    if (tid < HID) b1s[tid] = b1[tid];
    for (int i = tid; i < HID * 3; i += THREADS) w2s[i] = W2[i];
    if (tid < 3) b2s[tid] = b2[tid];
    __syncthreads();

    __half* Aw = reinterpret_cast<__half*>(sm + SOFF_A) + wid * 16 * STRH;

    // ldmatrix lane address templates
    const int arow = (lid & 7) + ((lid >> 3) & 1) * 8;
    const int acol = ((lid >> 4) & 1) * 8;
    const uint32_t aAddr0 = smb + SOFF_A + (uint32_t)(wid * 16 + arow) * STRB + acol * 2;
    // B x4: lanes 0-7 -> n0-7/k0, 8-15 -> n0-7/k8, 16-23 -> n8-15/k0, 24-31 -> n8-15/k8
    const int brow = (lid & 7) + ((lid >> 4) & 1) * 8;
    const int bcol16 = ((lid >> 3) & 1) * 16;     // bytes
    const uint32_t bAddr0 = smb + SOFF_B + (uint32_t)brow * STRB + bcol16;

    const int gstride = gridDim.x * WPB;
    for (int g = blockIdx.x * WPB + wid; g < GROUPS; g += gstride) {
        const int e0 = g * 16;

        // ---- phase A: per-edge meta (lanes 0-15, one edge each; kept in registers) ----
        int r_reg = 0, c_reg = 0, rn_reg = 0;
        float dxr = 0.f, dyr = 0.f, dzr = 0.f, ddr = 0.f;
        if (lid < 16) {
            int e = e0 + lid;
            r_reg = ei[e];
            c_reg = ei[NEDGES + e];
            rn_reg = r_reg;
            dxr = pos[3 * r_reg + 0] - pos[3 * c_reg + 0];
            dyr = pos[3 * r_reg + 1] - pos[3 * c_reg + 1];
            dzr = pos[3 * r_reg + 2] - pos[3 * c_reg + 2];
            ddr = sqrtf(dxr * dxr + dyr * dyr + dzr * dzr);
            __half* Ar = Aw + lid * STRH;
            #pragma unroll
            for (int k2 = 274; k2 < 288; k2 += 2)
                *reinterpret_cast<uint32_t*>(Ar + k2) = 0u;
            __half2 dh = __floats2half2_rn(ddr, 0.f);
            *reinterpret_cast<__half2*>(Ar + 272) = dh;
        }
        __syncwarp();

        // ---- phase B: gather features + edge_attr into A rows ----
        #pragma unroll 2
        for (int i = 0; i < 16; ++i) {
            int r = __shfl_sync(0xffffffffu, r_reg, i);
            int c = __shfl_sync(0xffffffffu, c_reg, i);
            __half* Ar = Aw + i * STRH;
            const uint2* fr = reinterpret_cast<const uint2*>(g_featH + (size_t)r * HID);
            const uint2* fc = reinterpret_cast<const uint2*>(g_featH + (size_t)c * HID);
            *reinterpret_cast<uint2*>(Ar + 4 * lid)       = fr[lid];
            *reinterpret_cast<uint2*>(Ar + 128 + 4 * lid) = fc[lid];
            if (lid < 8) {
                float2 a2 = reinterpret_cast<const float2*>(edge_attr)[(size_t)(e0 + i) * 8 + lid];
                *reinterpret_cast<__half2*>(Ar + 256 + 2 * lid) = __floats2half2_rn(a2.x, a2.y);
            }
        }
        __syncwarp();

        // ---- GEMM1: D[16x128] = A[16x288] * W1^T, fp32 accum in registers ----
        float acc[16][4];
        #pragma unroll
        for (int nt = 0; nt < 16; ++nt) {
            acc[nt][0] = 0.f; acc[nt][1] = 0.f; acc[nt][2] = 0.f; acc[nt][3] = 0.f;
        }
        uint32_t aA = aAddr0;
        uint32_t bA = bAddr0;
        #pragma unroll 1
        for (int ks = 0; ks < KSTEPS; ++ks) {
            uint32_t a0, a1, a2r, a3;
            asm volatile("ldmatrix.sync.aligned.m8n8.x4.shared.b16 {%0,%1,%2,%3}, [%4];"
                         : "=r"(a0), "=r"(a1), "=r"(a2r), "=r"(a3) : "r"(aA));
            #pragma unroll
            for (int nt2 = 0; nt2 < 8; ++nt2) {
                uint32_t b0, b1r, b2r, b3;
                asm volatile("ldmatrix.sync.aligned.m8n8.x4.shared.b16 {%0,%1,%2,%3}, [%4];"
                             : "=r"(b0), "=r"(b1r), "=r"(b2r), "=r"(b3)
                             : "r"(bA + (uint32_t)nt2 * 16 * STRB));
                asm volatile("mma.sync.aligned.m16n8k16.row.col.f32.f16.f16.f32 "
                             "{%0,%1,%2,%3}, {%4,%5,%6,%7}, {%8,%9}, {%0,%1,%2,%3};"
                             : "+f"(acc[2*nt2][0]), "+f"(acc[2*nt2][1]), "+f"(acc[2*nt2][2]), "+f"(acc[2*nt2][3])
                             : "r"(a0), "r"(a1), "r"(a2r), "r"(a3), "r"(b0), "r"(b1r));
                asm volatile("mma.sync.aligned.m16n8k16.row.col.f32.f16.f16.f32 "
                             "{%0,%1,%2,%3}, {%4,%5,%6,%7}, {%8,%9}, {%0,%1,%2,%3};"
                             : "+f"(acc[2*nt2+1][0]), "+f"(acc[2*nt2+1][1]), "+f"(acc[2*nt2+1][2]), "+f"(acc[2*nt2+1][3])
                             : "r"(a0), "r"(a1), "r"(a2r), "r"(a3), "r"(b2r), "r"(b3));
            }
            aA += 32;
            bA += 32;
        }

        // ---- epilogue: silu(h+b1), dot with W2 (3 cols), quad-reduce ----
        float p00 = 0.f, p01 = 0.f, p02 = 0.f, p10 = 0.f, p11 = 0.f, p12 = 0.f;
        const int cbase = (lid & 3) * 2;
        #pragma unroll
        for (int nt = 0; nt < 16; ++nt) {
            int n = nt * 8 + cbase;
            float h0 = silu(acc[nt][0] + b1s[n]);
            float h1 = silu(acc[nt][1] + b1s[n + 1]);
            float h2 = silu(acc[nt][2] + b1s[n]);
            float h3 = silu(acc[nt][3] + b1s[n + 1]);
            float wa0 = w2s[n * 3 + 0], wb0 = w2s[n * 3 + 1], wc0 = w2s[n * 3 + 2];
            float wa1 = w2s[n * 3 + 3], wb1 = w2s[n * 3 + 4], wc1 = w2s[n * 3 + 5];
            p00 += h0 * wa0 + h1 * wa1;
            p01 += h0 * wb0 + h1 * wb1;
            p02 += h0 * wc0 + h1 * wc1;
            p10 += h2 * wa0 + h3 * wa1;
            p11 += h2 * wb0 + h3 * wb1;
            p12 += h2 * wc0 + h3 * wc1;
        }
        #pragma unroll
        for (int off = 1; off <= 2; off <<= 1) {
            p00 += __shfl_xor_sync(0xffffffffu, p00, off);
            p01 += __shfl_xor_sync(0xffffffffu, p01, off);
            p02 += __shfl_xor_sync(0xffffffffu, p02, off);
            p10 += __shfl_xor_sync(0xffffffffu, p10, off);
            p11 += __shfl_xor_sync(0xffffffffu, p11, off);
            p12 += __shfl_xor_sync(0xffffffffu, p12, off);
        }

        const int gq = lid >> 2;
        const float s3 = 1.7320508075688772f;
        #pragma unroll
        for (int half = 0; half < 2; ++half) {
            int rowi = gq + half * 8;
            // fetch per-edge meta from the owning lane (whole warp participates)
            float ddx = __shfl_sync(0xffffffffu, dxr, rowi);
            float ddy = __shfl_sync(0xffffffffu, dyr, rowi);
            float ddz = __shfl_sync(0xffffffffu, dzr, rowi);
            float ddd = __shfl_sync(0xffffffffu, ddr, rowi);
            int   rn  = __shfl_sync(0xffffffffu, rn_reg, rowi);
            if ((lid & 3) == 0) {
                float pa = half ? p10 : p00;
                float pb = half ? p11 : p01;
                float pc = half ? p12 : p02;
                float w0 = silu(pa + b2s[0]);
                float w1 = silu(pb + b2s[1]);
                float w2v = silu(pc + b2s[2]);
                float inv = 1.f / fmaxf(ddd, 1e-12f);
                float x = ddx * inv, y = ddy * inv, z = ddz * inv;
                float* o = out + (size_t)rn * 9;
                atomicAdd(o + 0, w0);
                atomicAdd(o + 1, x * w1);
                atomicAdd(o + 2, y * w1);
                atomicAdd(o + 3, z * w1);
                atomicAdd(o + 4, s3 * x * z * w2v);
                atomicAdd(o + 5, s3 * x * y * w2v);
                atomicAdd(o + 6, (y * y - 0.5f * (x * x + z * z)) * w2v);
                atomicAdd(o + 7, s3 * y * z * w2v);
                atomicAdd(o + 8, 0.5f * s3 * (z * z - x * x) * w2v);
                atomicAdd(&g_cnt[rn], 1.0f);
            }
        }
        // no CTA barrier needed: all hot-loop state is warp-private
    }
}

// ---------------- launch ----------------
extern "C" void kernel_launch(void* const* d_in, const int* in_sizes, int n_in,
                              void* d_out, int out_size) {
    const float* node_feat = (const float*)d_in[0];
    const float* node_pos  = (const float*)d_in[1];
    const float* edge_attr = (const float*)d_in[2];
    const float* W1        = (const float*)d_in[3];
    const float* b1        = (const float*)d_in[4];
    const float* W2        = (const float*)d_in[5];
    const float* b2        = (const float*)d_in[6];
    const int*   ei        = (const int*)d_in[7];
    float* out = (float*)d_out;

    cudaFuncSetAttribute(edge_kernel,
                         cudaFuncAttributeMaxDynamicSharedMemorySize, SMEM_DYN);

    zero_kernel<<<512, 256>>>(out);
    prep_feat_kernel<<<(NNODES * HID / 2 + 255) / 256, 256>>>(node_feat);
    prep_w1_kernel<<<(HID * KDIM + 255) / 256, 256>>>(W1);
    edge_kernel<<<152, THREADS, SMEM_DYN>>>(node_pos, edge_attr, b1, W2, b2, ei, out);
    finalize_kernel<<<512, 256>>>(out);
}

// round 4
// speedup vs baseline: 1.8867x; 1.1127x over previous
#include <cuda_runtime.h>
#include <cuda_fp16.h>
#include <stdint.h>

// ---------------- problem constants ----------------
#define NNODES 50000
#define NEDGES 1000000
#define HID    128
#define KDIM   288            // 273 padded to 18 * 16
#define KSTEPS 18
#define STRH   296            // halves per smem row (592 B; 592 % 128 = 80 -> conflict-free ldmatrix)
#define STRB   592            // bytes per smem row
#define GROUPS (NEDGES / 16)  // 62500, exact (no tail)
#define WPB    16             // warps per block
#define THREADS 512

// ---------------- smem layout (byte offsets) ----------------
#define SOFF_A    0            // 256 rows * 592 = 151552
#define SOFF_B    151552       // 128 rows * 592 = 75776  -> ends 227328
#define SOFF_B1   227328       // 128 f32 = 512
#define SOFF_W2   227840       // 384 f32 = 1536
#define SOFF_B2   229376       // 16
#define SMEM_DYN  229392

// ---------------- device globals (no allocation allowed) ----------------
__device__ __half g_featH[(size_t)NNODES * HID];
__device__ __half g_W1h[HID * KDIM];     // [n][k] fp16, zero-padded k>=273
__device__ float  g_cnt[NNODES];

static __device__ __forceinline__ uint32_t smem_u32(const void* p) {
    uint32_t a;
    asm("{ .reg .u64 t; cvta.to.shared.u64 t, %1; cvt.u32.u64 %0, t; }" : "=r"(a) : "l"(p));
    return a;
}
static __device__ __forceinline__ float silu(float x) { return x / (1.f + __expf(-x)); }

// ---------------- prep kernels ----------------
__global__ void prep_feat_kernel(const float* __restrict__ nf) {
    int i = blockIdx.x * blockDim.x + threadIdx.x;
    const int tot = NNODES * HID / 2;
    if (i < tot) {
        float2 v = reinterpret_cast<const float2*>(nf)[i];
        reinterpret_cast<__half2*>(g_featH)[i] = __floats2half2_rn(v.x, v.y);
    }
}

// our k-order: [0..127]=feat_row, [128..255]=feat_col, [256..271]=edge_attr, [272]=dist, pad->288
// msg order  : [0]=dist, [1..128]=feat_row, [129..256]=feat_col, [257..272]=edge_attr
__global__ void prep_w1_kernel(const float* __restrict__ W1) {
    int idx = blockIdx.x * blockDim.x + threadIdx.x;
    if (idx >= HID * KDIM) return;
    int n = idx / KDIM, k = idx % KDIM;
    float v = 0.f;
    if (k < 273) {
        int orig = (k == 272) ? 0 : (k + 1);
        v = W1[orig * HID + n];
    }
    g_W1h[n * KDIM + k] = __float2half(v);
}

__global__ void zero_kernel(float* __restrict__ out) {
    int i = blockIdx.x * blockDim.x + threadIdx.x;
    int stride = gridDim.x * blockDim.x;
    for (int j = i; j < NNODES * 9; j += stride) out[j] = 0.f;
    for (int j = i; j < NNODES; j += stride) g_cnt[j] = 0.f;
}

__global__ void finalize_kernel(float* __restrict__ out) {
    int i = blockIdx.x * blockDim.x + threadIdx.x;
    int stride = gridDim.x * blockDim.x;
    for (int j = i; j < NNODES * 9; j += stride)
        out[j] = out[j] / fmaxf(g_cnt[j / 9], 1.0f);
}

// ---------------- main persistent kernel ----------------
__global__ void __launch_bounds__(THREADS, 1)
edge_kernel(const float* __restrict__ pos,
            const float* __restrict__ edge_attr,
            const float* __restrict__ b1,
            const float* __restrict__ W2,
            const float* __restrict__ b2,
            const int*   __restrict__ ei,
            float*       __restrict__ out)
{
    extern __shared__ char sm[];
    const uint32_t smb = smem_u32(sm);
    const int tid = threadIdx.x;
    const int wid = tid >> 5;
    const int lid = tid & 31;

    // stage W1 [n][k] fp16 into smem with padded row stride
    {
        const uint32_t* src = reinterpret_cast<const uint32_t*>(g_W1h);
        uint32_t* dst = reinterpret_cast<uint32_t*>(sm + SOFF_B);
        for (int i = tid; i < HID * (KDIM / 2); i += THREADS) {
            int n = i / (KDIM / 2), k2 = i % (KDIM / 2);
            dst[n * (STRH / 2) + k2] = src[i];
        }
    }
    float* b1s = reinterpret_cast<float*>(sm + SOFF_B1);
    float* w2s = reinterpret_cast<float*>(sm + SOFF_W2);
    float* b2s = reinterpret_cast<float*>(sm + SOFF_B2);
    if (tid < HID) b1s[tid] = b1[tid];
    for (int i = tid; i < HID * 3; i += THREADS) w2s[i] = W2[i];
    if (tid < 3) b2s[tid] = b2[tid];
    __syncthreads();

    __half* Aw = reinterpret_cast<__half*>(sm + SOFF_A) + wid * 16 * STRH;
    const __half* featH = g_featH;

    // ldmatrix lane address templates
    const int arow = (lid & 7) + ((lid >> 3) & 1) * 8;
    const int acol = ((lid >> 4) & 1) * 8;
    const uint32_t aAddr0 = smb + SOFF_A + (uint32_t)(wid * 16 + arow) * STRB + acol * 2;
    // B x4: lanes 0-7 -> n0-7/k0, 8-15 -> n0-7/k8, 16-23 -> n8-15/k0, 24-31 -> n8-15/k8
    const int brow = (lid & 7) + ((lid >> 4) & 1) * 8;
    const int bcol16 = ((lid >> 3) & 1) * 16;     // bytes
    const uint32_t bAddr0 = smb + SOFF_B + (uint32_t)brow * STRB + bcol16;

    const int gstride = gridDim.x * WPB;
    for (int g = blockIdx.x * WPB + wid; g < GROUPS; g += gstride) {
        const int e0 = g * 16;

        // ---- phase A: per-edge meta (lanes 0-15, one edge each; kept in registers) ----
        int r_reg = 0, c_reg = 0, rn_reg = 0;
        float dxr = 0.f, dyr = 0.f, dzr = 0.f, ddr = 0.f;
        if (lid < 16) {
            int e = e0 + lid;
            r_reg = ei[e];
            c_reg = ei[NEDGES + e];
            rn_reg = r_reg;
            dxr = pos[3 * r_reg + 0] - pos[3 * c_reg + 0];
            dyr = pos[3 * r_reg + 1] - pos[3 * c_reg + 1];
            dzr = pos[3 * r_reg + 2] - pos[3 * c_reg + 2];
            ddr = sqrtf(dxr * dxr + dyr * dyr + dzr * dzr);
            __half* Ar = Aw + lid * STRH;
            #pragma unroll
            for (int k2 = 274; k2 < 288; k2 += 2)
                *reinterpret_cast<uint32_t*>(Ar + k2) = 0u;
            __half2 dh = __floats2half2_rn(ddr, 0.f);
            *reinterpret_cast<__half2*>(Ar + 272) = dh;
        }
        __syncwarp();

        // ---- phase B: gather features, MLP-optimized (load-all then store-all, 8 rows/batch) ----
        #pragma unroll
        for (int pass = 0; pass < 2; ++pass) {
            uint2 vr[8], vc[8];
            #pragma unroll
            for (int i = 0; i < 8; ++i) {
                int row = pass * 8 + i;
                int r = __shfl_sync(0xffffffffu, r_reg, row);
                int c = __shfl_sync(0xffffffffu, c_reg, row);
                vr[i] = reinterpret_cast<const uint2*>(featH + (size_t)r * HID)[lid];
                vc[i] = reinterpret_cast<const uint2*>(featH + (size_t)c * HID)[lid];
            }
            #pragma unroll
            for (int i = 0; i < 8; ++i) {
                __half* Ar = Aw + (pass * 8 + i) * STRH;
                *reinterpret_cast<uint2*>(Ar + 4 * lid)       = vr[i];
                *reinterpret_cast<uint2*>(Ar + 128 + 4 * lid) = vc[i];
            }
        }
        // edge_attr: 128 float2 loads spread across all 32 lanes (4 each, batched)
        {
            float2 a2v[4];
            #pragma unroll
            for (int j = 0; j < 4; ++j) {
                int idx = lid + 32 * j;
                int row = idx >> 3, sl = idx & 7;
                a2v[j] = reinterpret_cast<const float2*>(edge_attr)[(size_t)(e0 + row) * 8 + sl];
            }
            #pragma unroll
            for (int j = 0; j < 4; ++j) {
                int idx = lid + 32 * j;
                int row = idx >> 3, sl = idx & 7;
                __half* Ar = Aw + row * STRH;
                *reinterpret_cast<__half2*>(Ar + 256 + 2 * sl) = __floats2half2_rn(a2v[j].x, a2v[j].y);
            }
        }
        __syncwarp();

        // ---- GEMM1: D[16x128] = A[16x288] * W1^T, fp32 accum in registers ----
        float acc[16][4];
        #pragma unroll
        for (int nt = 0; nt < 16; ++nt) {
            acc[nt][0] = 0.f; acc[nt][1] = 0.f; acc[nt][2] = 0.f; acc[nt][3] = 0.f;
        }
        uint32_t aA = aAddr0;
        uint32_t bA = bAddr0;
        #pragma unroll 1
        for (int ks = 0; ks < KSTEPS; ++ks) {
            uint32_t a0, a1, a2r, a3;
            asm volatile("ldmatrix.sync.aligned.m8n8.x4.shared.b16 {%0,%1,%2,%3}, [%4];"
                         : "=r"(a0), "=r"(a1), "=r"(a2r), "=r"(a3) : "r"(aA));
            #pragma unroll
            for (int nt2 = 0; nt2 < 8; ++nt2) {
                uint32_t b0, b1r, b2r, b3;
                asm volatile("ldmatrix.sync.aligned.m8n8.x4.shared.b16 {%0,%1,%2,%3}, [%4];"
                             : "=r"(b0), "=r"(b1r), "=r"(b2r), "=r"(b3)
                             : "r"(bA + (uint32_t)nt2 * 16 * STRB));
                asm volatile("mma.sync.aligned.m16n8k16.row.col.f32.f16.f16.f32 "
                             "{%0,%1,%2,%3}, {%4,%5,%6,%7}, {%8,%9}, {%0,%1,%2,%3};"
                             : "+f"(acc[2*nt2][0]), "+f"(acc[2*nt2][1]), "+f"(acc[2*nt2][2]), "+f"(acc[2*nt2][3])
                             : "r"(a0), "r"(a1), "r"(a2r), "r"(a3), "r"(b0), "r"(b1r));
                asm volatile("mma.sync.aligned.m16n8k16.row.col.f32.f16.f16.f32 "
                             "{%0,%1,%2,%3}, {%4,%5,%6,%7}, {%8,%9}, {%0,%1,%2,%3};"
                             : "+f"(acc[2*nt2+1][0]), "+f"(acc[2*nt2+1][1]), "+f"(acc[2*nt2+1][2]), "+f"(acc[2*nt2+1][3])
                             : "r"(a0), "r"(a1), "r"(a2r), "r"(a3), "r"(b2r), "r"(b3));
            }
            aA += 32;
            bA += 32;
        }

        // ---- epilogue: silu(h+b1), dot with W2 (3 cols), quad-reduce ----
        float p00 = 0.f, p01 = 0.f, p02 = 0.f, p10 = 0.f, p11 = 0.f, p12 = 0.f;
        const int cbase = (lid & 3) * 2;
        #pragma unroll
        for (int nt = 0; nt < 16; ++nt) {
            int n = nt * 8 + cbase;
            float h0 = silu(acc[nt][0] + b1s[n]);
            float h1 = silu(acc[nt][1] + b1s[n + 1]);
            float h2 = silu(acc[nt][2] + b1s[n]);
            float h3 = silu(acc[nt][3] + b1s[n + 1]);
            float wa0 = w2s[n * 3 + 0], wb0 = w2s[n * 3 + 1], wc0 = w2s[n * 3 + 2];
            float wa1 = w2s[n * 3 + 3], wb1 = w2s[n * 3 + 4], wc1 = w2s[n * 3 + 5];
            p00 += h0 * wa0 + h1 * wa1;
            p01 += h0 * wb0 + h1 * wb1;
            p02 += h0 * wc0 + h1 * wc1;
            p10 += h2 * wa0 + h3 * wa1;
            p11 += h2 * wb0 + h3 * wb1;
            p12 += h2 * wc0 + h3 * wc1;
        }
        #pragma unroll
        for (int off = 1; off <= 2; off <<= 1) {
            p00 += __shfl_xor_sync(0xffffffffu, p00, off);
            p01 += __shfl_xor_sync(0xffffffffu, p01, off);
            p02 += __shfl_xor_sync(0xffffffffu, p02, off);
            p10 += __shfl_xor_sync(0xffffffffu, p10, off);
            p11 += __shfl_xor_sync(0xffffffffu, p11, off);
            p12 += __shfl_xor_sync(0xffffffffu, p12, off);
        }

        const int gq = lid >> 2;
        const float s3 = 1.7320508075688772f;
        #pragma unroll
        for (int half = 0; half < 2; ++half) {
            int rowi = gq + half * 8;
            // fetch per-edge meta from the owning lane (whole warp participates)
            float ddx = __shfl_sync(0xffffffffu, dxr, rowi);
            float ddy = __shfl_sync(0xffffffffu, dyr, rowi);
            float ddz = __shfl_sync(0xffffffffu, dzr, rowi);
            float ddd = __shfl_sync(0xffffffffu, ddr, rowi);
            int   rn  = __shfl_sync(0xffffffffu, rn_reg, rowi);
            if ((lid & 3) == 0) {
                float pa = half ? p10 : p00;
                float pb = half ? p11 : p01;
                float pc = half ? p12 : p02;
                float w0 = silu(pa + b2s[0]);
                float w1 = silu(pb + b2s[1]);
                float w2v = silu(pc + b2s[2]);
                float inv = 1.f / fmaxf(ddd, 1e-12f);
                float x = ddx * inv, y = ddy * inv, z = ddz * inv;
                float* o = out + (size_t)rn * 9;
                atomicAdd(o + 0, w0);
                atomicAdd(o + 1, x * w1);
                atomicAdd(o + 2, y * w1);
                atomicAdd(o + 3, z * w1);
                atomicAdd(o + 4, s3 * x * z * w2v);
                atomicAdd(o + 5, s3 * x * y * w2v);
                atomicAdd(o + 6, (y * y - 0.5f * (x * x + z * z)) * w2v);
                atomicAdd(o + 7, s3 * y * z * w2v);
                atomicAdd(o + 8, 0.5f * s3 * (z * z - x * x) * w2v);
                atomicAdd(&g_cnt[rn], 1.0f);
            }
        }
        // no CTA barrier needed: all hot-loop state is warp-private
    }
}

// ---------------- launch ----------------
extern "C" void kernel_launch(void* const* d_in, const int* in_sizes, int n_in,
                              void* d_out, int out_size) {
    const float* node_feat = (const float*)d_in[0];
    const float* node_pos  = (const float*)d_in[1];
    const float* edge_attr = (const float*)d_in[2];
    const float* W1        = (const float*)d_in[3];
    const float* b1        = (const float*)d_in[4];
    const float* W2        = (const float*)d_in[5];
    const float* b2        = (const float*)d_in[6];
    const int*   ei        = (const int*)d_in[7];
    float* out = (float*)d_out;

    cudaFuncSetAttribute(edge_kernel,
                         cudaFuncAttributeMaxDynamicSharedMemorySize, SMEM_DYN);

    zero_kernel<<<512, 256>>>(out);
    prep_feat_kernel<<<(NNODES * HID / 2 + 255) / 256, 256>>>(node_feat);
    prep_w1_kernel<<<(HID * KDIM + 255) / 256, 256>>>(W1);
    edge_kernel<<<152, THREADS, SMEM_DYN>>>(node_pos, edge_attr, b1, W2, b2, ei, out);
    finalize_kernel<<<512, 256>>>(out);
}

// round 5
// speedup vs baseline: 1.9783x; 1.0486x over previous
#include <cuda_runtime.h>
#include <cuda_fp16.h>
#include <stdint.h>

// ---------------- problem constants ----------------
#define NNODES 50000
#define NEDGES 1000000
#define HID    128
#define KDIM   288            // 273 padded to 18 * 16
#define KSTEPS 18
#define STRH   296            // halves per smem row (592 B; 592 % 128 = 80 -> conflict-free ldmatrix)
#define STRB   592            // bytes per smem row
#define GROUPS32 (NEDGES / 32) // 31250, exact
#define WPB    16             // warps per block (8 pairs)
#define THREADS 512

// ---------------- smem layout (byte offsets) ----------------
#define SOFF_A    0            // 256 rows * 592 = 151552 (bytes 576..591 of each row = pad, used for partials)
#define SOFF_B    151552       // 128 rows * 592 = 75776  -> ends 227328
#define SOFF_B1   227328       // 128 f32 = 512
#define SOFF_W2   227840       // 384 f32 = 1536
#define SOFF_B2   229376       // 16
#define SMEM_DYN  229392
#define PAD_OFF   576          // per-row pad byte offset (12 B used of 16)

// ---------------- device globals (no allocation allowed) ----------------
__device__ __half g_featH[(size_t)NNODES * HID];
__device__ __half g_W1h[HID * KDIM];     // [n][k] fp16, zero-padded k>=273
__device__ float  g_cnt[NNODES];

static __device__ __forceinline__ uint32_t smem_u32(const void* p) {
    uint32_t a;
    asm("{ .reg .u64 t; cvta.to.shared.u64 t, %1; cvt.u32.u64 %0, t; }" : "=r"(a) : "l"(p));
    return a;
}
static __device__ __forceinline__ float silu(float x) { return x / (1.f + __expf(-x)); }
static __device__ __forceinline__ void pair_bar(int id) {
    asm volatile("bar.sync %0, 64;" :: "r"(id) : "memory");
}

// ---------------- prep kernels ----------------
__global__ void prep_feat_kernel(const float* __restrict__ nf) {
    int i = blockIdx.x * blockDim.x + threadIdx.x;
    const int tot = NNODES * HID / 2;
    if (i < tot) {
        float2 v = reinterpret_cast<const float2*>(nf)[i];
        reinterpret_cast<__half2*>(g_featH)[i] = __floats2half2_rn(v.x, v.y);
    }
}

// our k-order: [0..127]=feat_row, [128..255]=feat_col, [256..271]=edge_attr, [272]=dist, pad->288
__global__ void prep_w1_kernel(const float* __restrict__ W1) {
    int idx = blockIdx.x * blockDim.x + threadIdx.x;
    if (idx >= HID * KDIM) return;
    int n = idx / KDIM, k = idx % KDIM;
    float v = 0.f;
    if (k < 273) {
        int orig = (k == 272) ? 0 : (k + 1);
        v = W1[orig * HID + n];
    }
    g_W1h[n * KDIM + k] = __float2half(v);
}

__global__ void zero_kernel(float* __restrict__ out) {
    int i = blockIdx.x * blockDim.x + threadIdx.x;
    int stride = gridDim.x * blockDim.x;
    for (int j = i; j < NNODES * 9; j += stride) out[j] = 0.f;
    for (int j = i; j < NNODES; j += stride) g_cnt[j] = 0.f;
}

__global__ void finalize_kernel(float* __restrict__ out) {
    int i = blockIdx.x * blockDim.x + threadIdx.x;
    int stride = gridDim.x * blockDim.x;
    for (int j = i; j < NNODES * 9; j += stride)
        out[j] = out[j] / fmaxf(g_cnt[j / 9], 1.0f);
}

// ---------------- main persistent kernel ----------------
__global__ void __launch_bounds__(THREADS, 1)
edge_kernel(const float* __restrict__ pos,
            const float* __restrict__ edge_attr,
            const float* __restrict__ b1,
            const float* __restrict__ W2,
            const float* __restrict__ b2,
            const int*   __restrict__ ei,
            float*       __restrict__ out)
{
    extern __shared__ char sm[];
    const uint32_t smb = smem_u32(sm);
    const int tid = threadIdx.x;
    const int wid = tid >> 5;
    const int lid = tid & 31;
    const int pairL = wid >> 1;          // 0..7
    const int par   = wid & 1;           // 0 = even warp (owns rows 0-15 of pair), 1 = odd

    // stage W1 [n][k] fp16 into smem with padded row stride
    {
        const uint32_t* src = reinterpret_cast<const uint32_t*>(g_W1h);
        uint32_t* dst = reinterpret_cast<uint32_t*>(sm + SOFF_B);
        for (int i = tid; i < HID * (KDIM / 2); i += THREADS) {
            int n = i / (KDIM / 2), k2 = i % (KDIM / 2);
            dst[n * (STRH / 2) + k2] = src[i];
        }
    }
    float* b1s = reinterpret_cast<float*>(sm + SOFF_B1);
    float* w2s = reinterpret_cast<float*>(sm + SOFF_W2);
    float* b2s = reinterpret_cast<float*>(sm + SOFF_B2);
    if (tid < HID) b1s[tid] = b1[tid];
    for (int i = tid; i < HID * 3; i += THREADS) w2s[i] = W2[i];
    if (tid < 3) b2s[tid] = b2[tid];
    __syncthreads();

    // this warp's own 16 rows in the pair's 32-row slab
    const int slabRow0 = pairL * 32;               // pair slab base row
    const int ownRow0  = slabRow0 + par * 16;      // this warp's rows
    __half* Aw = reinterpret_cast<__half*>(sm + SOFF_A) + ownRow0 * STRH;
    const __half* featH = g_featH;

    // ldmatrix lane address templates
    const int arow = (lid & 7) + ((lid >> 3) & 1) * 8;
    const int acol = ((lid >> 4) & 1) * 8;
    // A tile mt covers slab rows slabRow0 + mt*16
    const uint32_t aAddrMt0 = smb + SOFF_A + (uint32_t)(slabRow0 + arow) * STRB + acol * 2;
    const uint32_t aAddrMt1 = aAddrMt0 + 16u * STRB;
    // B x4: lanes 0-7 -> n0-7/k0, 8-15 -> n0-7/k8, 16-23 -> n8-15/k0, 24-31 -> n8-15/k8
    const int brow = (lid & 7) + ((lid >> 4) & 1) * 8;
    const int bcol16 = ((lid >> 3) & 1) * 16;     // bytes
    const int nhalf = par * 64;                    // this warp's n-column half
    const uint32_t bAddr0 = smb + SOFF_B + (uint32_t)(nhalf + brow) * STRB + bcol16;

    const int barId = pairL + 1;
    const int gq = lid >> 2;

    const int gstride = gridDim.x * (WPB / 2);
    for (int g = blockIdx.x * (WPB / 2) + pairL; g < GROUPS32; g += gstride) {
        const int e0own = g * 32 + par * 16;

        // ---- phase A: per-edge meta (lanes 0-15, one edge each; kept in registers) ----
        int r_reg = 0, c_reg = 0, rn_reg = 0;
        float dxr = 0.f, dyr = 0.f, dzr = 0.f, ddr = 0.f;
        if (lid < 16) {
            int e = e0own + lid;
            r_reg = ei[e];
            c_reg = ei[NEDGES + e];
            rn_reg = r_reg;
            dxr = pos[3 * r_reg + 0] - pos[3 * c_reg + 0];
            dyr = pos[3 * r_reg + 1] - pos[3 * c_reg + 1];
            dzr = pos[3 * r_reg + 2] - pos[3 * c_reg + 2];
            ddr = sqrtf(dxr * dxr + dyr * dyr + dzr * dzr);
            __half* Ar = Aw + lid * STRH;
            #pragma unroll
            for (int k2 = 274; k2 < 288; k2 += 2)
                *reinterpret_cast<uint32_t*>(Ar + k2) = 0u;
            __half2 dh = __floats2half2_rn(ddr, 0.f);
            *reinterpret_cast<__half2*>(Ar + 272) = dh;
        }
        __syncwarp();

        // ---- phase B: gather features into own 16 rows (load-all then store-all) ----
        #pragma unroll
        for (int pass = 0; pass < 2; ++pass) {
            uint2 vr[8], vc[8];
            #pragma unroll
            for (int i = 0; i < 8; ++i) {
                int row = pass * 8 + i;
                int r = __shfl_sync(0xffffffffu, r_reg, row);
                int c = __shfl_sync(0xffffffffu, c_reg, row);
                vr[i] = reinterpret_cast<const uint2*>(featH + (size_t)r * HID)[lid];
                vc[i] = reinterpret_cast<const uint2*>(featH + (size_t)c * HID)[lid];
            }
            #pragma unroll
            for (int i = 0; i < 8; ++i) {
                __half* Ar = Aw + (pass * 8 + i) * STRH;
                *reinterpret_cast<uint2*>(Ar + 4 * lid)       = vr[i];
                *reinterpret_cast<uint2*>(Ar + 128 + 4 * lid) = vc[i];
            }
        }
        // edge_attr: 128 float2 loads spread across 32 lanes (4 each, batched)
        {
            float2 a2v[4];
            #pragma unroll
            for (int j = 0; j < 4; ++j) {
                int idx = lid + 32 * j;
                int row = idx >> 3, sl = idx & 7;
                a2v[j] = reinterpret_cast<const float2*>(edge_attr)[(size_t)(e0own + row) * 8 + sl];
            }
            #pragma unroll
            for (int j = 0; j < 4; ++j) {
                int idx = lid + 32 * j;
                int row = idx >> 3, sl = idx & 7;
                __half* Ar = Aw + row * STRH;
                *reinterpret_cast<__half2*>(Ar + 256 + 2 * sl) = __floats2half2_rn(a2v[j].x, a2v[j].y);
            }
        }
        pair_bar(barId);   // both warps' 16 rows built

        // ---- GEMM1: D[32 x 64] = A_pair[32x288] * W1half^T, fp32 accum ----
        float acc[2][8][4];
        #pragma unroll
        for (int mt = 0; mt < 2; ++mt)
            #pragma unroll
            for (int nt = 0; nt < 8; ++nt) {
                acc[mt][nt][0] = 0.f; acc[mt][nt][1] = 0.f;
                acc[mt][nt][2] = 0.f; acc[mt][nt][3] = 0.f;
            }
        uint32_t aA0 = aAddrMt0, aA1 = aAddrMt1, bA = bAddr0;
        #pragma unroll 1
        for (int ks = 0; ks < KSTEPS; ++ks) {
            uint32_t x0, x1, x2, x3, y0, y1, y2, y3;
            asm volatile("ldmatrix.sync.aligned.m8n8.x4.shared.b16 {%0,%1,%2,%3}, [%4];"
                         : "=r"(x0), "=r"(x1), "=r"(x2), "=r"(x3) : "r"(aA0));
            asm volatile("ldmatrix.sync.aligned.m8n8.x4.shared.b16 {%0,%1,%2,%3}, [%4];"
                         : "=r"(y0), "=r"(y1), "=r"(y2), "=r"(y3) : "r"(aA1));
            #pragma unroll
            for (int j = 0; j < 4; ++j) {
                uint32_t b0, b1r, b2r, b3;
                asm volatile("ldmatrix.sync.aligned.m8n8.x4.shared.b16 {%0,%1,%2,%3}, [%4];"
                             : "=r"(b0), "=r"(b1r), "=r"(b2r), "=r"(b3)
                             : "r"(bA + (uint32_t)j * 16 * STRB));
                asm volatile("mma.sync.aligned.m16n8k16.row.col.f32.f16.f16.f32 "
                             "{%0,%1,%2,%3}, {%4,%5,%6,%7}, {%8,%9}, {%0,%1,%2,%3};"
                             : "+f"(acc[0][2*j][0]), "+f"(acc[0][2*j][1]), "+f"(acc[0][2*j][2]), "+f"(acc[0][2*j][3])
                             : "r"(x0), "r"(x1), "r"(x2), "r"(x3), "r"(b0), "r"(b1r));
                asm volatile("mma.sync.aligned.m16n8k16.row.col.f32.f16.f16.f32 "
                             "{%0,%1,%2,%3}, {%4,%5,%6,%7}, {%8,%9}, {%0,%1,%2,%3};"
                             : "+f"(acc[0][2*j+1][0]), "+f"(acc[0][2*j+1][1]), "+f"(acc[0][2*j+1][2]), "+f"(acc[0][2*j+1][3])
                             : "r"(x0), "r"(x1), "r"(x2), "r"(x3), "r"(b2r), "r"(b3));
                asm volatile("mma.sync.aligned.m16n8k16.row.col.f32.f16.f16.f32 "
                             "{%0,%1,%2,%3}, {%4,%5,%6,%7}, {%8,%9}, {%0,%1,%2,%3};"
                             : "+f"(acc[1][2*j][0]), "+f"(acc[1][2*j][1]), "+f"(acc[1][2*j][2]), "+f"(acc[1][2*j][3])
                             : "r"(y0), "r"(y1), "r"(y2), "r"(y3), "r"(b0), "r"(b1r));
                asm volatile("mma.sync.aligned.m16n8k16.row.col.f32.f16.f16.f32 "
                             "{%0,%1,%2,%3}, {%4,%5,%6,%7}, {%8,%9}, {%0,%1,%2,%3};"
                             : "+f"(acc[1][2*j+1][0]), "+f"(acc[1][2*j+1][1]), "+f"(acc[1][2*j+1][2]), "+f"(acc[1][2*j+1][3])
                             : "r"(y0), "r"(y1), "r"(y2), "r"(y3), "r"(b2r), "r"(b3));
            }
            aA0 += 32; aA1 += 32; bA += 32;
        }

        // ---- partial epilogue: silu(h+b1), dot with W2 over this warp's 64 n's ----
        float pr[2][2][3];
        #pragma unroll
        for (int mt = 0; mt < 2; ++mt)
            #pragma unroll
            for (int hf = 0; hf < 2; ++hf) {
                pr[mt][hf][0] = 0.f; pr[mt][hf][1] = 0.f; pr[mt][hf][2] = 0.f;
            }
        const int cbase = (lid & 3) * 2;
        #pragma unroll
        for (int mt = 0; mt < 2; ++mt) {
            #pragma unroll
            for (int nt = 0; nt < 8; ++nt) {
                int n = nhalf + nt * 8 + cbase;
                float h0 = silu(acc[mt][nt][0] + b1s[n]);
                float h1 = silu(acc[mt][nt][1] + b1s[n + 1]);
                float h2 = silu(acc[mt][nt][2] + b1s[n]);
                float h3 = silu(acc[mt][nt][3] + b1s[n + 1]);
                float wa0 = w2s[n * 3 + 0], wb0 = w2s[n * 3 + 1], wc0 = w2s[n * 3 + 2];
                float wa1 = w2s[n * 3 + 3], wb1 = w2s[n * 3 + 4], wc1 = w2s[n * 3 + 5];
                pr[mt][0][0] += h0 * wa0 + h1 * wa1;
                pr[mt][0][1] += h0 * wb0 + h1 * wb1;
                pr[mt][0][2] += h0 * wc0 + h1 * wc1;
                pr[mt][1][0] += h2 * wa0 + h3 * wa1;
                pr[mt][1][1] += h2 * wb0 + h3 * wb1;
                pr[mt][1][2] += h2 * wc0 + h3 * wc1;
            }
        }
        #pragma unroll
        for (int off = 1; off <= 2; off <<= 1) {
            #pragma unroll
            for (int mt = 0; mt < 2; ++mt)
                #pragma unroll
                for (int hf = 0; hf < 2; ++hf) {
                    pr[mt][hf][0] += __shfl_xor_sync(0xffffffffu, pr[mt][hf][0], off);
                    pr[mt][hf][1] += __shfl_xor_sync(0xffffffffu, pr[mt][hf][1], off);
                    pr[mt][hf][2] += __shfl_xor_sync(0xffffffffu, pr[mt][hf][2], off);
                }
        }

        // deposit partials for the NON-owned mt into those rows' pad bytes
        const int mtNon = 1 - par;
        if ((lid & 3) == 0) {
            #pragma unroll
            for (int hf = 0; hf < 2; ++hf) {
                int rowNon = slabRow0 + mtNon * 16 + gq + hf * 8;
                float* pad = reinterpret_cast<float*>(sm + SOFF_A + (size_t)rowNon * STRB + PAD_OFF);
                pad[0] = pr[mtNon][hf][0];
                pad[1] = pr[mtNon][hf][1];
                pad[2] = pr[mtNon][hf][2];
            }
        }
        pair_bar(barId);   // partials visible

        // ---- final epilogue for this warp's own 16 edges ----
        const float s3 = 1.7320508075688772f;
        const int mtOwn = par;
        #pragma unroll
        for (int hf = 0; hf < 2; ++hf) {
            int rloc = gq + hf * 8;   // local edge index 0..15
            float ddx = __shfl_sync(0xffffffffu, dxr, rloc);
            float ddy = __shfl_sync(0xffffffffu, dyr, rloc);
            float ddz = __shfl_sync(0xffffffffu, dzr, rloc);
            float ddd = __shfl_sync(0xffffffffu, ddr, rloc);
            int   rn  = __shfl_sync(0xffffffffu, rn_reg, rloc);
            if ((lid & 3) == 0) {
                int rowOwn = ownRow0 + rloc;
                const float* pad = reinterpret_cast<const float*>(sm + SOFF_A + (size_t)rowOwn * STRB + PAD_OFF);
                float pa = pr[mtOwn][hf][0] + pad[0];
                float pb = pr[mtOwn][hf][1] + pad[1];
                float pc = pr[mtOwn][hf][2] + pad[2];
                float w0 = silu(pa + b2s[0]);
                float w1 = silu(pb + b2s[1]);
                float w2v = silu(pc + b2s[2]);
                float inv = 1.f / fmaxf(ddd, 1e-12f);
                float x = ddx * inv, y = ddy * inv, z = ddz * inv;
                float* o = out + (size_t)rn * 9;
                atomicAdd(o + 0, w0);
                atomicAdd(o + 1, x * w1);
                atomicAdd(o + 2, y * w1);
                atomicAdd(o + 3, z * w1);
                atomicAdd(o + 4, s3 * x * z * w2v);
                atomicAdd(o + 5, s3 * x * y * w2v);
                atomicAdd(o + 6, (y * y - 0.5f * (x * x + z * z)) * w2v);
                atomicAdd(o + 7, s3 * y * z * w2v);
                atomicAdd(o + 8, 0.5f * s3 * (z * z - x * x) * w2v);
                atomicAdd(&g_cnt[rn], 1.0f);
            }
        }
        // next iteration's pair_bar(barId) orders A-row rebuild vs this group's reads
    }
}

// ---------------- launch ----------------
extern "C" void kernel_launch(void* const* d_in, const int* in_sizes, int n_in,
                              void* d_out, int out_size) {
    const float* node_feat = (const float*)d_in[0];
    const float* node_pos  = (const float*)d_in[1];
    const float* edge_attr = (const float*)d_in[2];
    const float* W1        = (const float*)d_in[3];
    const float* b1        = (const float*)d_in[4];
    const float* W2        = (const float*)d_in[5];
    const float* b2        = (const float*)d_in[6];
    const int*   ei        = (const int*)d_in[7];
    float* out = (float*)d_out;

    cudaFuncSetAttribute(edge_kernel,
                         cudaFuncAttributeMaxDynamicSharedMemorySize, SMEM_DYN);

    zero_kernel<<<512, 256>>>(out);
    prep_feat_kernel<<<(NNODES * HID / 2 + 255) / 256, 256>>>(node_feat);
    prep_w1_kernel<<<(HID * KDIM + 255) / 256, 256>>>(W1);
    edge_kernel<<<152, THREADS, SMEM_DYN>>>(node_pos, edge_attr, b1, W2, b2, ei, out);
    finalize_kernel<<<512, 256>>>(out);
}